// round 1
// baseline (speedup 1.0000x reference)
#include <cuda_runtime.h>
#include <math.h>

#define N_USERS 100000
#define N_ITEMS 50000
#define N_NODES 150000
#define NNZ     4800000
#define EMB     64
#define N_LAYERS 3
#define BATCH   4096
#define REG_C   1e-5f
#define NE      (N_NODES * EMB)   // 9,600,000 floats per plane

// Scratch: 4 embedding planes (ego + 3 normalized layer outputs) + SpMM accumulator
__device__ float g_X[(N_LAYERS + 1) * NE];   // 153.6 MB
__device__ float g_sideL[NE];                // 38.4 MB

// ---------------------------------------------------------------------------
// ego = concat(user_emb, item_emb)  -> g_X plane 0
// ---------------------------------------------------------------------------
__global__ void ego_copy_kernel(const float* __restrict__ ue,
                                const float* __restrict__ ie) {
    int idx = blockIdx.x * blockDim.x + threadIdx.x;  // float4 index
    const int UF = (N_USERS * EMB) / 4;
    const int TF = NE / 4;
    if (idx >= TF) return;
    float4 v = (idx < UF) ? ((const float4*)ue)[idx]
                          : ((const float4*)ie)[idx - UF];
    ((float4*)g_X)[idx] = v;
}

// ---------------------------------------------------------------------------
// zero the SpMM accumulator
// ---------------------------------------------------------------------------
__global__ void zero_sideL_kernel() {
    int idx = blockIdx.x * blockDim.x + threadIdx.x;
    if (idx < NE / 4) ((float4*)g_sideL)[idx] = make_float4(0.f, 0.f, 0.f, 0.f);
}

// ---------------------------------------------------------------------------
// SpMM: sideL[rows[e]] += vals[e] * x[cols[e]]
// 16 lanes per edge, each lane handles a float4 (4 cols). One coalesced 256B
// gather + 16x red.global.add.v4.f32 (no-return reduction) per edge.
// ---------------------------------------------------------------------------
__global__ void spmm_kernel(const int*   __restrict__ rows,
                            const int*   __restrict__ cols,
                            const float* __restrict__ vals,
                            int layer) {
    int t    = blockIdx.x * blockDim.x + threadIdx.x;
    int e    = t >> 4;
    int lane = t & 15;
    if (e >= NNZ) return;

    const float* __restrict__ x = g_X + layer * NE;

    int   r = __ldg(rows + e);
    int   c = __ldg(cols + e);
    float v = __ldg(vals + e);

    float4 xv = *(const float4*)(x + c * EMB + lane * 4);
    float* dst = g_sideL + r * EMB + lane * 4;
    asm volatile("red.global.add.v4.f32 [%0], {%1,%2,%3,%4};"
                 :: "l"(dst), "f"(v * xv.x), "f"(v * xv.y),
                    "f"(v * xv.z), "f"(v * xv.w)
                 : "memory");
}

// ---------------------------------------------------------------------------
// Fused layer: for each row,
//   li = sideL + x ; inter = sideL * x
//   e  = leaky_relu(li @ W1 + b1 + inter @ W2 + b2, 0.01)
//   out = e / max(||e||_2, 1e-12)
// Block = 256 threads = 16 rows x 16 col-groups (4 cols each).
// W1/W2 + combined bias + staged activations in smem.
// ---------------------------------------------------------------------------
__global__ void layer_kernel(const float* __restrict__ W1,
                             const float* __restrict__ b1,
                             const float* __restrict__ W2,
                             const float* __restrict__ b2,
                             int layer) {
    __shared__ __align__(16) float W1s[64][64];
    __shared__ __align__(16) float W2s[64][64];
    __shared__ __align__(16) float bs[64];
    __shared__ __align__(16) float li_s[16][64];
    __shared__ __align__(16) float in_s[16][64];

    const float* __restrict__ xk = g_X + layer * NE;
    float* __restrict__ xout     = g_X + (layer + 1) * NE;

    int tid = threadIdx.x;
    for (int idx = tid; idx < 4096; idx += 256) {
        ((float*)W1s)[idx] = W1[idx];
        ((float*)W2s)[idx] = W2[idx];
    }
    if (tid < 64) bs[tid] = b1[tid] + b2[tid];

    int r   = tid >> 4;        // local row 0..15
    int jg  = tid & 15;        // col group 0..15
    int row = blockIdx.x * 16 + r;

    float4 s4 = *(const float4*)(g_sideL + row * EMB + jg * 4);
    float4 a4 = *(const float4*)(xk      + row * EMB + jg * 4);
    float4 li = make_float4(s4.x + a4.x, s4.y + a4.y, s4.z + a4.z, s4.w + a4.w);
    float4 in = make_float4(s4.x * a4.x, s4.y * a4.y, s4.z * a4.z, s4.w * a4.w);
    *(float4*)&li_s[r][jg * 4] = li;
    *(float4*)&in_s[r][jg * 4] = in;
    __syncthreads();

    float4 acc = *(const float4*)&bs[jg * 4];
#pragma unroll 16
    for (int k = 0; k < 64; k++) {
        float f = li_s[r][k];
        float g = in_s[r][k];
        float4 w1 = *(const float4*)&W1s[k][jg * 4];
        float4 w2 = *(const float4*)&W2s[k][jg * 4];
        acc.x += f * w1.x + g * w2.x;
        acc.y += f * w1.y + g * w2.y;
        acc.z += f * w1.z + g * w2.z;
        acc.w += f * w1.w + g * w2.w;
    }

    // leaky relu (slope 0.01)
    float4 e;
    e.x = acc.x > 0.f ? acc.x : 0.01f * acc.x;
    e.y = acc.y > 0.f ? acc.y : 0.01f * acc.y;
    e.z = acc.z > 0.f ? acc.z : 0.01f * acc.z;
    e.w = acc.w > 0.f ? acc.w : 0.01f * acc.w;

    // row L2 norm across the 16 lanes of this half-warp (offsets 1,2,4,8 stay
    // inside a 16-lane group)
    float ss = e.x * e.x + e.y * e.y + e.z * e.z + e.w * e.w;
    ss += __shfl_xor_sync(0xffffffff, ss, 1);
    ss += __shfl_xor_sync(0xffffffff, ss, 2);
    ss += __shfl_xor_sync(0xffffffff, ss, 4);
    ss += __shfl_xor_sync(0xffffffff, ss, 8);
    float nrm = fmaxf(sqrtf(ss), 1e-12f);
    float inv = 1.0f / nrm;

    float4 o = make_float4(e.x * inv, e.y * inv, e.z * inv, e.w * inv);
    *(float4*)(xout + row * EMB + jg * 4) = o;
}

// ---------------------------------------------------------------------------
// zero the scalar output (d_out is poisoned to 0xAA)
// ---------------------------------------------------------------------------
__global__ void zero_out_kernel(float* out) {
    if (blockIdx.x == 0 && threadIdx.x == 0) *out = 0.f;
}

// ---------------------------------------------------------------------------
// BPR loss + L2 reg. One warp per batch element; dot over the 4 concatenated
// 64-dim chunks; warp shuffle reduce; block reduce; one atomicAdd per block.
// ---------------------------------------------------------------------------
__global__ void loss_kernel(const int* __restrict__ u,
                            const int* __restrict__ ii,
                            const int* __restrict__ jj,
                            float* __restrict__ out) {
    int gw   = (blockIdx.x * blockDim.x + threadIdx.x) >> 5;
    int lane = threadIdx.x & 31;

    float contrib = 0.f;
    if (gw < BATCH) {
        int uu = u[gw];
        int pi = N_USERS + ii[gw];
        int nj = N_USERS + jj[gw];

        float dui = 0.f, duj = 0.f, l2 = 0.f;
#pragma unroll
        for (int c = 0; c < N_LAYERS + 1; c++) {
            const float* base = g_X + c * NE;
            float2 uv = *(const float2*)(base + uu * EMB + lane * 2);
            float2 pv = *(const float2*)(base + pi * EMB + lane * 2);
            float2 nv = *(const float2*)(base + nj * EMB + lane * 2);
            dui += uv.x * pv.x + uv.y * pv.y;
            duj += uv.x * nv.x + uv.y * nv.y;
            l2  += uv.x * uv.x + uv.y * uv.y
                 + pv.x * pv.x + pv.y * pv.y
                 + nv.x * nv.x + nv.y * nv.y;
        }
#pragma unroll
        for (int o = 16; o; o >>= 1) {
            dui += __shfl_xor_sync(0xffffffff, dui, o);
            duj += __shfl_xor_sync(0xffffffff, duj, o);
            l2  += __shfl_xor_sync(0xffffffff, l2,  o);
        }
        if (lane == 0) {
            float xv = dui - duj;
            // stable log_sigmoid(x) = min(x,0) - log1p(exp(-|x|))
            float ls = fminf(xv, 0.f) - log1pf(expf(-fabsf(xv)));
            contrib = (-ls + REG_C * 0.5f * l2) * (1.0f / (float)BATCH);
        }
    }

    __shared__ float sred[8];
    if (lane == 0) sred[threadIdx.x >> 5] = contrib;
    __syncthreads();
    if (threadIdx.x == 0) {
        float s = 0.f;
#pragma unroll
        for (int q = 0; q < 8; q++) s += sred[q];
        atomicAdd(out, s);
    }
}

// ---------------------------------------------------------------------------
extern "C" void kernel_launch(void* const* d_in, const int* in_sizes, int n_in,
                              void* d_out, int out_size) {
    const int*   rows     = (const int*)  d_in[0];
    const int*   cols     = (const int*)  d_in[1];
    const float* vals     = (const float*)d_in[2];
    const float* user_emb = (const float*)d_in[3];
    const float* item_emb = (const float*)d_in[4];
    const float* W_one    = (const float*)d_in[5];
    const float* b_one    = (const float*)d_in[6];
    const float* W_two    = (const float*)d_in[7];
    const float* b_two    = (const float*)d_in[8];
    const int*   u        = (const int*)  d_in[9];
    const int*   i        = (const int*)  d_in[10];
    const int*   j        = (const int*)  d_in[11];
    float* out = (float*)d_out;

    (void)in_sizes; (void)n_in; (void)out_size;

    const int VEC_BLOCKS = (NE / 4 + 255) / 256;   // 9375

    ego_copy_kernel<<<VEC_BLOCKS, 256>>>(user_emb, item_emb);

    for (int k = 0; k < N_LAYERS; k++) {
        zero_sideL_kernel<<<VEC_BLOCKS, 256>>>();
        spmm_kernel<<<(NNZ * 16) / 256, 256>>>(rows, cols, vals, k);
        layer_kernel<<<N_NODES / 16, 256>>>(W_one + k * EMB * EMB,
                                            b_one + k * EMB,
                                            W_two + k * EMB * EMB,
                                            b_two + k * EMB,
                                            k);
    }

    zero_out_kernel<<<1, 32>>>(out);
    loss_kernel<<<BATCH / 8, 256>>>(u, i, j, out);
}

// round 2
// speedup vs baseline: 2.3647x; 2.3647x over previous
#include <cuda_runtime.h>
#include <math.h>

#define N_USERS 100000
#define N_NODES 150000
#define NNZ     4800000
#define EMB     64
#define N_LAYERS 3
#define BATCH   4096
#define REG_C   1e-5f
#define NE      (N_NODES * EMB)
#define HIST_SZ 150016
#define HIST_BLOCKS 586

typedef unsigned long long u64;

// ---------------- scratch (alloc-free rule: __device__ globals) ------------
__device__ float g_X[(N_LAYERS + 1) * NE];   // 153.6 MB: ego + 3 layer outputs
__device__ float g_sideL[NE];                // 38.4 MB
__device__ int   g_hist[HIST_SZ];
__device__ int   g_row_start[HIST_SZ];       // exclusive scan (+tail = NNZ)
__device__ int   g_cursor[HIST_SZ];
__device__ int   g_blocksum[HIST_BLOCKS];
__device__ uint2 g_edges[NNZ];               // (col, val) sorted by row

// ---------------- f32x2 packed-math helpers --------------------------------
__device__ __forceinline__ u64 pack2(float lo, float hi) {
    u64 r; asm("mov.b64 %0,{%1,%2};" : "=l"(r) : "f"(lo), "f"(hi)); return r;
}
__device__ __forceinline__ void unpack2(u64 v, float& lo, float& hi) {
    asm("mov.b64 {%0,%1},%2;" : "=f"(lo), "=f"(hi) : "l"(v));
}
__device__ __forceinline__ u64 fma2(u64 a, u64 b, u64 c) {
    u64 d; asm("fma.rn.f32x2 %0,%1,%2,%3;" : "=l"(d) : "l"(a), "l"(b), "l"(c));
    return d;
}

// ---------------- ego = concat(user_emb, item_emb) -------------------------
__global__ void ego_copy_kernel(const float* __restrict__ ue,
                                const float* __restrict__ ie) {
    int idx = blockIdx.x * blockDim.x + threadIdx.x;
    const int UF = (N_USERS * EMB) / 4;
    const int TF = NE / 4;
    if (idx >= TF) return;
    float4 v = (idx < UF) ? ((const float4*)ue)[idx]
                          : ((const float4*)ie)[idx - UF];
    ((float4*)g_X)[idx] = v;
}

// ---------------- CSR build: hist -> scan -> scatter ------------------------
__global__ void zero_hist_kernel() {
    int i = blockIdx.x * 256 + threadIdx.x;
    if (i < HIST_SZ) g_hist[i] = 0;
}

__global__ void hist_kernel(const int* __restrict__ rows) {
    int e = blockIdx.x * 256 + threadIdx.x;
    if (e < NNZ) atomicAdd(&g_hist[rows[e]], 1);
}

__global__ void scan1_kernel() {   // per-256-block exclusive scan + block sums
    __shared__ int s[256];
    int t = threadIdx.x;
    int i = blockIdx.x * 256 + t;
    int v = g_hist[i];
    s[t] = v; __syncthreads();
#pragma unroll
    for (int off = 1; off < 256; off <<= 1) {
        int add = (t >= off) ? s[t - off] : 0;
        __syncthreads();
        s[t] += add;
        __syncthreads();
    }
    g_row_start[i] = s[t] - v;                    // local exclusive
    if (t == 255) g_blocksum[blockIdx.x] = s[255];
}

__global__ void scan2_kernel() {   // scan the 586 block sums (1 block)
    __shared__ int s[1024];
    int t = threadIdx.x;
    int v = (t < HIST_BLOCKS) ? g_blocksum[t] : 0;
    s[t] = v; __syncthreads();
#pragma unroll
    for (int off = 1; off < 1024; off <<= 1) {
        int add = (t >= off) ? s[t - off] : 0;
        __syncthreads();
        s[t] += add;
        __syncthreads();
    }
    if (t < HIST_BLOCKS) g_blocksum[t] = s[t] - v;  // exclusive
}

__global__ void scan3_kernel() {   // add block prefix; init cursors
    int i = blockIdx.x * 256 + threadIdx.x;
    int v = g_row_start[i] + g_blocksum[blockIdx.x];
    g_row_start[i] = v;
    g_cursor[i]    = v;
}

__global__ void scatter_kernel(const int* __restrict__ rows,
                               const int* __restrict__ cols,
                               const float* __restrict__ vals) {
    int e = blockIdx.x * 256 + threadIdx.x;
    if (e >= NNZ) return;
    int r = rows[e];
    int pos = atomicAdd(&g_cursor[r], 1);
    g_edges[pos] = make_uint2((unsigned)cols[e], __float_as_uint(vals[e]));
}

// ---------------- SpMM (CSR, output-stationary): warp per row ---------------
__global__ void spmm_csr_kernel(int layer) {
    int w    = (blockIdx.x * blockDim.x + threadIdx.x) >> 5;
    int lane = threadIdx.x & 31;
    if (w >= N_NODES) return;
    const float* __restrict__ x = g_X + layer * NE;
    int s = __ldg(&g_row_start[w]);
    int e = __ldg(&g_row_start[w + 1]);

    float ax = 0.f, ay = 0.f;
    int t = s;
    for (; t + 4 <= e; t += 4) {   // MLP=4 independent gathers
        uint2 k0 = g_edges[t + 0];
        uint2 k1 = g_edges[t + 1];
        uint2 k2 = g_edges[t + 2];
        uint2 k3 = g_edges[t + 3];
        float2 x0 = *(const float2*)(x + (size_t)k0.x * EMB + lane * 2);
        float2 x1 = *(const float2*)(x + (size_t)k1.x * EMB + lane * 2);
        float2 x2 = *(const float2*)(x + (size_t)k2.x * EMB + lane * 2);
        float2 x3 = *(const float2*)(x + (size_t)k3.x * EMB + lane * 2);
        float v0 = __uint_as_float(k0.y), v1 = __uint_as_float(k1.y);
        float v2 = __uint_as_float(k2.y), v3 = __uint_as_float(k3.y);
        ax += v0 * x0.x + v1 * x1.x + v2 * x2.x + v3 * x3.x;
        ay += v0 * x0.y + v1 * x1.y + v2 * x2.y + v3 * x3.y;
    }
    for (; t < e; t++) {
        uint2 kv = g_edges[t];
        float2 xv = *(const float2*)(x + (size_t)kv.x * EMB + lane * 2);
        float v = __uint_as_float(kv.y);
        ax += v * xv.x;
        ay += v * xv.y;
    }
    *(float2*)(g_sideL + (size_t)w * EMB + lane * 2) = make_float2(ax, ay);
}

// ---------------- Fused layer: GEMMx2 + bias + leaky + row-normalize --------
// Block 256 = 16 col-groups (jg, 4 cols) x 16 row-threads (rt, 4 rows strided
// by 16) -> 64 rows/block. li+in interleaved float2 tile, XOR bank swizzle
// col ^ ((row&3)<<2). W1/W2 staged in smem. Packed f32x2 FMA.
__global__ void layer_kernel(const float* __restrict__ W1,
                             const float* __restrict__ b1,
                             const float* __restrict__ W2,
                             const float* __restrict__ b2,
                             int layer) {
    extern __shared__ float sm[];
    float*  W1s   = sm;                       // 4096 floats
    float*  W2s   = sm + 4096;                // 4096 floats
    float2* li_in = (float2*)(sm + 8192);     // 64x64 float2 (32KB)

    const float* __restrict__ xk = g_X + (size_t)layer * NE;
    float* __restrict__ xo       = g_X + (size_t)(layer + 1) * NE;

    int tid = threadIdx.x;
#pragma unroll
    for (int it = 0; it < 4; it++) {
        int idx = it * 256 + tid;             // 1024 float4 per matrix
        ((float4*)W1s)[idx] = ((const float4*)W1)[idx];
        ((float4*)W2s)[idx] = ((const float4*)W2)[idx];
    }

    int jg = tid & 15;
    int rt = tid >> 4;
    int sw = (rt & 3) << 2;                   // row swizzle (row&3 == rt&3)
    int cb = (jg * 4) ^ sw;                   // swizzled col base (mult of 4)
    int base_row = blockIdx.x * 64;

    // stage li = sideL + x, in = sideL * x (interleaved, swizzled)
#pragma unroll
    for (int q = 0; q < 4; q++) {
        int rl = rt + 16 * q;
        int rg = base_row + rl;
        float4 li4, in4;
        if (rg < N_NODES) {
            float4 s4 = *(const float4*)(g_sideL + (size_t)rg * EMB + jg * 4);
            float4 a4 = *(const float4*)(xk      + (size_t)rg * EMB + jg * 4);
            li4 = make_float4(s4.x + a4.x, s4.y + a4.y, s4.z + a4.z, s4.w + a4.w);
            in4 = make_float4(s4.x * a4.x, s4.y * a4.y, s4.z * a4.z, s4.w * a4.w);
        } else {
            li4 = make_float4(0.f, 0.f, 0.f, 0.f);
            in4 = li4;
        }
        float2* p = &li_in[rl * 64 + cb];
        *(float4*)(p)     = make_float4(li4.x, in4.x, li4.y, in4.y);
        *(float4*)(p + 2) = make_float4(li4.z, in4.z, li4.w, in4.w);
    }
    __syncthreads();

    float4 bb1 = *(const float4*)(b1 + jg * 4);
    float4 bb2 = *(const float4*)(b2 + jg * 4);
    u64 acc01[4], acc23[4];
    {
        u64 i01 = pack2(bb1.x + bb2.x, bb1.y + bb2.y);
        u64 i23 = pack2(bb1.z + bb2.z, bb1.w + bb2.w);
#pragma unroll
        for (int q = 0; q < 4; q++) { acc01[q] = i01; acc23[q] = i23; }
    }

#pragma unroll 4
    for (int k = 0; k < 64; k++) {
        float4 w1 = *(const float4*)&W1s[k * 64 + jg * 4];
        float4 w2 = *(const float4*)&W2s[k * 64 + jg * 4];
        u64 w1a = pack2(w1.x, w1.y), w1b = pack2(w1.z, w1.w);
        u64 w2a = pack2(w2.x, w2.y), w2b = pack2(w2.z, w2.w);
        int kc = k ^ sw;
#pragma unroll
        for (int q = 0; q < 4; q++) {
            int rl = rt + 16 * q;
            float2 fg = li_in[rl * 64 + kc];
            u64 ff = pack2(fg.x, fg.x);
            u64 gg = pack2(fg.y, fg.y);
            acc01[q] = fma2(ff, w1a, acc01[q]);
            acc01[q] = fma2(gg, w2a, acc01[q]);
            acc23[q] = fma2(ff, w1b, acc23[q]);
            acc23[q] = fma2(gg, w2b, acc23[q]);
        }
    }

#pragma unroll
    for (int q = 0; q < 4; q++) {
        int rg = base_row + rt + 16 * q;
        float a0, a1, a2, a3;
        unpack2(acc01[q], a0, a1);
        unpack2(acc23[q], a2, a3);
        a0 = a0 > 0.f ? a0 : 0.01f * a0;
        a1 = a1 > 0.f ? a1 : 0.01f * a1;
        a2 = a2 > 0.f ? a2 : 0.01f * a2;
        a3 = a3 > 0.f ? a3 : 0.01f * a3;
        float ss = a0 * a0 + a1 * a1 + a2 * a2 + a3 * a3;
        ss += __shfl_xor_sync(0xffffffffu, ss, 1);
        ss += __shfl_xor_sync(0xffffffffu, ss, 2);
        ss += __shfl_xor_sync(0xffffffffu, ss, 4);
        ss += __shfl_xor_sync(0xffffffffu, ss, 8);
        float inv = 1.0f / fmaxf(sqrtf(ss), 1e-12f);
        if (rg < N_NODES)
            *(float4*)(xo + (size_t)rg * EMB + jg * 4) =
                make_float4(a0 * inv, a1 * inv, a2 * inv, a3 * inv);
    }
}

// ---------------- output zero + BPR loss ------------------------------------
__global__ void zero_out_kernel(float* out) {
    if (blockIdx.x == 0 && threadIdx.x == 0) *out = 0.f;
}

__global__ void loss_kernel(const int* __restrict__ u,
                            const int* __restrict__ ii,
                            const int* __restrict__ jj,
                            float* __restrict__ out) {
    int gw   = (blockIdx.x * blockDim.x + threadIdx.x) >> 5;
    int lane = threadIdx.x & 31;

    float contrib = 0.f;
    if (gw < BATCH) {
        int uu = u[gw];
        int pi = N_USERS + ii[gw];
        int nj = N_USERS + jj[gw];
        float dui = 0.f, duj = 0.f, l2 = 0.f;
#pragma unroll
        for (int c = 0; c < N_LAYERS + 1; c++) {
            const float* base = g_X + (size_t)c * NE;
            float2 uv = *(const float2*)(base + (size_t)uu * EMB + lane * 2);
            float2 pv = *(const float2*)(base + (size_t)pi * EMB + lane * 2);
            float2 nv = *(const float2*)(base + (size_t)nj * EMB + lane * 2);
            dui += uv.x * pv.x + uv.y * pv.y;
            duj += uv.x * nv.x + uv.y * nv.y;
            l2  += uv.x * uv.x + uv.y * uv.y
                 + pv.x * pv.x + pv.y * pv.y
                 + nv.x * nv.x + nv.y * nv.y;
        }
#pragma unroll
        for (int o = 16; o; o >>= 1) {
            dui += __shfl_xor_sync(0xffffffffu, dui, o);
            duj += __shfl_xor_sync(0xffffffffu, duj, o);
            l2  += __shfl_xor_sync(0xffffffffu, l2,  o);
        }
        if (lane == 0) {
            float xv = dui - duj;
            float ls = fminf(xv, 0.f) - log1pf(expf(-fabsf(xv)));
            contrib = (-ls + REG_C * 0.5f * l2) * (1.0f / (float)BATCH);
        }
    }

    __shared__ float sred[8];
    if (lane == 0) sred[threadIdx.x >> 5] = contrib;
    __syncthreads();
    if (threadIdx.x == 0) {
        float s = 0.f;
#pragma unroll
        for (int q = 0; q < 8; q++) s += sred[q];
        atomicAdd(out, s);
    }
}

// ---------------------------------------------------------------------------
extern "C" void kernel_launch(void* const* d_in, const int* in_sizes, int n_in,
                              void* d_out, int out_size) {
    const int*   rows     = (const int*)  d_in[0];
    const int*   cols     = (const int*)  d_in[1];
    const float* vals     = (const float*)d_in[2];
    const float* user_emb = (const float*)d_in[3];
    const float* item_emb = (const float*)d_in[4];
    const float* W_one    = (const float*)d_in[5];
    const float* b_one    = (const float*)d_in[6];
    const float* W_two    = (const float*)d_in[7];
    const float* b_two    = (const float*)d_in[8];
    const int*   u        = (const int*)  d_in[9];
    const int*   i        = (const int*)  d_in[10];
    const int*   j        = (const int*)  d_in[11];
    float* out = (float*)d_out;
    (void)in_sizes; (void)n_in; (void)out_size;

    cudaFuncSetAttribute(layer_kernel,
                         cudaFuncAttributeMaxDynamicSharedMemorySize, 65536);

    ego_copy_kernel<<<(NE / 4 + 255) / 256, 256>>>(user_emb, item_emb);

    // CSR build (once per launch; rows constant across layers)
    zero_hist_kernel<<<HIST_BLOCKS, 256>>>();
    hist_kernel<<<NNZ / 256, 256>>>(rows);
    scan1_kernel<<<HIST_BLOCKS, 256>>>();
    scan2_kernel<<<1, 1024>>>();
    scan3_kernel<<<HIST_BLOCKS, 256>>>();
    scatter_kernel<<<NNZ / 256, 256>>>(rows, cols, vals);

    for (int k = 0; k < N_LAYERS; k++) {
        spmm_csr_kernel<<<(N_NODES * 32) / 256 + 1, 256>>>(k);
        layer_kernel<<<(N_NODES + 63) / 64, 256, 65536>>>(
            W_one + k * EMB * EMB, b_one + k * EMB,
            W_two + k * EMB * EMB, b_two + k * EMB, k);
    }

    zero_out_kernel<<<1, 32>>>(out);
    loss_kernel<<<BATCH / 8, 256>>>(u, i, j, out);
}